// round 2
// baseline (speedup 1.0000x reference)
#include <cuda_runtime.h>
#include <cuda_bf16.h>
#include <cstdint>
#include <cstddef>

#define T_LEN 2048
#define BATCH 16
#define HID   256
#define CIN   512
#define GATES 1024              // 4*H per direction
#define NCOL  2048              // gates for both directions
#define MROWS (BATCH * T_LEN)   // 32768

// ---------------- scratch (static device globals; no allocations) ----------
__device__ float g_proj[(size_t)MROWS * NCOL];            // 256 MB: input projection
__device__ float g_hs[(size_t)2 * T_LEN * BATCH * HID];   // 64 MB: h outputs [dir][t][b][c]
__device__ float g_part[128 * 512 * 2];                   // BN partial sums
__device__ float g_wf[4 * 512];                           // folded Wlin (2 outs x 512 ch)
__device__ float g_zc[2];                                 // folded bias
__device__ float g_sampled[BATCH * T_LEN];                // sampled signal pre-median

// ============================================================================
// K1: projection GEMM  proj[m][n] = sum_k x[b][k][t] * W[n][k]
//     m = b*T + t;  n < 1024 -> Wih_f rows, else Wih_b rows.
// fp32, 128x64 tile, BK=16, 256 threads, 8x4 per-thread microtile.
// ============================================================================
__global__ void gemm_proj(const float* __restrict__ X,
                          const float* __restrict__ Wf,
                          const float* __restrict__ Wb) {
    __shared__ float As[16][132];   // [k][m], padded
    __shared__ float Bs[16][68];    // [k][n], padded

    const int ntile = blockIdx.x;          // 0..31
    const int mtile = blockIdx.y;          // 0..255
    const int m0 = mtile * 128;
    const int n0 = ntile * 64;
    const int b  = m0 >> 11;               // T=2048 per batch, tiles never straddle b
    const int t0 = m0 & 2047;

    const float* W = (n0 < GATES) ? Wf : Wb;
    const int nr0 = (n0 < GATES) ? n0 : (n0 - GATES);

    const int tid = threadIdx.x;
    const int ty = tid >> 4;   // 0..15 -> 8 rows each
    const int tx = tid & 15;   // 0..15 -> 4 cols each

    float acc[8][4];
#pragma unroll
    for (int i = 0; i < 8; i++)
#pragma unroll
        for (int j = 0; j < 4; j++) acc[i][j] = 0.f;

    for (int k0 = 0; k0 < CIN; k0 += 16) {
        // load A tile: 128 x 16 (coalesced along t)
#pragma unroll
        for (int i = 0; i < 8; i++) {
            int idx = i * 256 + tid;
            int mm = idx & 127, kk = idx >> 7;
            As[kk][mm] = X[((size_t)b * CIN + (k0 + kk)) * T_LEN + t0 + mm];
        }
        // load B tile: 16 x 64 (contiguous 64B runs along k)
#pragma unroll
        for (int i = 0; i < 4; i++) {
            int idx = i * 256 + tid;
            int kk = idx & 15, n = idx >> 4;
            Bs[kk][n] = W[(size_t)(nr0 + n) * CIN + k0 + kk];
        }
        __syncthreads();

#pragma unroll
        for (int k = 0; k < 16; k++) {
            float4 a0 = *(const float4*)&As[k][ty * 8];
            float4 a1 = *(const float4*)&As[k][ty * 8 + 4];
            float4 bv = *(const float4*)&Bs[k][tx * 4];
            float av[8] = {a0.x, a0.y, a0.z, a0.w, a1.x, a1.y, a1.z, a1.w};
            float bw[4] = {bv.x, bv.y, bv.z, bv.w};
#pragma unroll
            for (int i = 0; i < 8; i++)
#pragma unroll
                for (int j = 0; j < 4; j++)
                    acc[i][j] += av[i] * bw[j];
        }
        __syncthreads();
    }

#pragma unroll
    for (int i = 0; i < 8; i++) {
        int m = m0 + ty * 8 + i;
        float4 v = make_float4(acc[i][0], acc[i][1], acc[i][2], acc[i][3]);
        *(float4*)&g_proj[(size_t)m * NCOL + n0 + tx * 4] = v;
    }
}

// ============================================================================
// K2: LSTM recurrence. 32 chains (dir,b) x 4-CTA clusters. Each CTA: 64 cells,
// 256 gate rows, Whh slice resident in smem as bf16 (128KB). h/c fp32.
// Per-step cross-CTA h broadcast via mapa + st.shared::cluster + cluster barrier.
// ============================================================================
__device__ __forceinline__ void cluster_sync_() {
    asm volatile("barrier.cluster.arrive.aligned;" ::: "memory");
    asm volatile("barrier.cluster.wait.aligned;" ::: "memory");
}

__device__ __forceinline__ float sigm_(float x) {
    return 1.f / (1.f + __expf(-x));
}

#define LSTM_SMEM (131072 + 2048 + 1024 + 256 + 1024)

__global__ void __cluster_dims__(4, 1, 1) lstm_k(
    const float* __restrict__ WhhF, const float* __restrict__ WhhB,
    const float* __restrict__ bihF, const float* __restrict__ bhhF,
    const float* __restrict__ bihB, const float* __restrict__ bhhB) {
    extern __shared__ char smem[];
    __nv_bfloat16* w = (__nv_bfloat16*)smem;              // [256][256] bf16
    float* hbuf  = (float*)(smem + 131072);               // [2][256]
    float* gates = hbuf + 512;                            // [256]
    float* cst   = gates + 256;                           // [64]
    float* bias  = cst + 64;                              // [256]

    const int tid = threadIdx.x;                          // 512 threads
    const int cbid = blockIdx.x;
    const int chain = cbid >> 2;                          // 0..31
    const int r = cbid & 3;                               // rank in cluster
    const int dir = chain >> 4;
    const int b = chain & 15;

    const float* Whh = dir ? WhhB : WhhF;
    const float* bih = dir ? bihB : bihF;
    const float* bhh = dir ? bhhB : bhhF;

    // load + convert weights: local gate row q -> global row (q>>6)*256 + r*64 + (q&63)
    for (int idx = tid; idx < 256 * 256; idx += 512) {
        int q = idx >> 8, k = idx & 255;
        int grow = ((q >> 6) << 8) + (r << 6) + (q & 63);
        w[idx] = __float2bfloat16(Whh[(size_t)grow * HID + k]);
    }
    if (tid < 256) {
        int grow = ((tid >> 6) << 8) + (r << 6) + (tid & 63);
        bias[tid] = bih[grow] + bhh[grow];
        hbuf[tid] = 0.f;
        hbuf[256 + tid] = 0.f;
    }
    if (tid < 64) cst[tid] = 0.f;
    __syncthreads();
    cluster_sync_();

    const int g  = tid >> 1;
    const int kh = (tid & 1) << 7;   // 0 or 128
    const int grow_g = ((g >> 6) << 8) + (r << 6) + (g & 63);
    const uint4* wrow = (const uint4*)(w + (size_t)g * 256 + kh);  // 16 x uint4
    const size_t proj_col = (size_t)dir * GATES + grow_g;

    int p = 0;
    for (int step = 0; step < T_LEN; step++) {
        const int te = dir ? (T_LEN - 1 - step) : step;
        const float4* hv = (const float4*)(hbuf + p * 256 + kh);

        float acc0 = 0.f, acc1 = 0.f;
#pragma unroll
        for (int c = 0; c < 16; c += 2) {
            uint4 wp = wrow[c];
            float4 h0 = hv[c * 2];
            float4 h1 = hv[c * 2 + 1];
            acc0 += __uint_as_float(wp.x << 16) * h0.x;
            acc0 += __uint_as_float(wp.x & 0xffff0000u) * h0.y;
            acc0 += __uint_as_float(wp.y << 16) * h0.z;
            acc0 += __uint_as_float(wp.y & 0xffff0000u) * h0.w;
            acc0 += __uint_as_float(wp.z << 16) * h1.x;
            acc0 += __uint_as_float(wp.z & 0xffff0000u) * h1.y;
            acc0 += __uint_as_float(wp.w << 16) * h1.z;
            acc0 += __uint_as_float(wp.w & 0xffff0000u) * h1.w;
            uint4 wq = wrow[c + 1];
            float4 h2 = hv[c * 2 + 2];
            float4 h3 = hv[c * 2 + 3];
            acc1 += __uint_as_float(wq.x << 16) * h2.x;
            acc1 += __uint_as_float(wq.x & 0xffff0000u) * h2.y;
            acc1 += __uint_as_float(wq.y << 16) * h2.z;
            acc1 += __uint_as_float(wq.y & 0xffff0000u) * h2.w;
            acc1 += __uint_as_float(wq.z << 16) * h3.x;
            acc1 += __uint_as_float(wq.z & 0xffff0000u) * h3.y;
            acc1 += __uint_as_float(wq.w << 16) * h3.z;
            acc1 += __uint_as_float(wq.w & 0xffff0000u) * h3.w;
        }
        float acc = acc0 + acc1;
        acc += __shfl_xor_sync(0xffffffffu, acc, 1);
        if ((tid & 1) == 0) {
            gates[g] = acc + bias[g] +
                       g_proj[(size_t)(b * T_LEN + te) * NCOL + proj_col];
        }
        __syncthreads();

        if (tid < 64) {
            float iv = sigm_(gates[tid]);
            float fv = sigm_(gates[64 + tid]);
            float gv = tanhf(gates[128 + tid]);
            float ov = sigm_(gates[192 + tid]);
            float c = fv * cst[tid] + iv * gv;
            cst[tid] = c;
            float hval = ov * tanhf(c);
            g_hs[(size_t)((dir * T_LEN + te) * BATCH + b) * HID + r * 64 + tid] = hval;

            int np = p ^ 1;
            float* dst = hbuf + np * 256 + r * 64 + tid;
            *dst = hval;  // local copy
            uint32_t la = (uint32_t)__cvta_generic_to_shared(dst);
#pragma unroll
            for (int pc = 0; pc < 4; pc++) {
                if (pc == r) continue;
                uint32_t ra;
                asm("mapa.shared::cluster.u32 %0, %1, %2;" : "=r"(ra) : "r"(la), "r"(pc));
                asm volatile("st.shared::cluster.f32 [%0], %1;" :: "r"(ra), "f"(hval)
                             : "memory");
            }
        }
        cluster_sync_();   // release remote stores, all CTAs see new h
        p ^= 1;
    }
}

// ============================================================================
// K3a: BN partial sums (coalesced). 128 blocks x 512 threads, 256 samples each.
// ============================================================================
__global__ void bn_part() {
    const int ch = threadIdx.x;       // 0..511; dir = ch>>8
    const int dir = ch >> 8, cc = ch & 255;
    const int s0 = blockIdx.x * 256;
    float sum = 0.f, sq = 0.f;
    const size_t base = (size_t)dir * T_LEN * BATCH * HID + cc;
    for (int i = 0; i < 256; i++) {
        float v = g_hs[base + (size_t)(s0 + i) * HID];
        sum += v; sq += v * v;
    }
    g_part[((size_t)blockIdx.x * 512 + ch) * 2]     = sum;
    g_part[((size_t)blockIdx.x * 512 + ch) * 2 + 1] = sq;
}

// ============================================================================
// K3b: finalize BN stats, fold into Linear: z_o = sum_c wf[o][c]*h[c] + zc[o]
// ============================================================================
__global__ void bn_final(const float* __restrict__ gamma,
                         const float* __restrict__ beta,
                         const float* __restrict__ Wlin,
                         const float* __restrict__ blin) {
    __shared__ float red[512];
    const int ch = threadIdx.x;
    double s = 0.0, q = 0.0;
    for (int i = 0; i < 128; i++) {
        s += (double)g_part[((size_t)i * 512 + ch) * 2];
        q += (double)g_part[((size_t)i * 512 + ch) * 2 + 1];
    }
    const double n = 32768.0;
    float mean = (float)(s / n);
    float var  = (float)(q / n - (s / n) * (s / n));
    float A  = gamma[ch] * rsqrtf(var + 1e-5f);
    float Bc = beta[ch] - mean * A;

    g_wf[ch]       = Wlin[ch] * A;          // output 0
    g_wf[512 + ch] = Wlin[512 + ch] * A;    // output 1

    red[ch] = Wlin[ch] * Bc;
    __syncthreads();
    for (int o = 256; o > 0; o >>= 1) {
        if (ch < o) red[ch] += red[ch + o];
        __syncthreads();
    }
    if (ch == 0) g_zc[0] = blin[0] + red[0];
    __syncthreads();
    red[ch] = Wlin[512 + ch] * Bc;
    __syncthreads();
    for (int o = 256; o > 0; o >>= 1) {
        if (ch < o) red[ch] += red[ch + o];
        __syncthreads();
    }
    if (ch == 0) g_zc[1] = blin[1] + red[0];
}

// ============================================================================
// K4: posterior + gumbel argmax + sampled. One warp per (t,b) sample.
// st forward value == y_hard; argmax(y) == argmax(z/10 + g).
// ============================================================================
__global__ void post_k(const float* __restrict__ u,
                       const float* __restrict__ e,
                       float* __restrict__ out) {
    const int s = blockIdx.x * 8 + (threadIdx.x >> 5);   // sample = t*16 + b
    const int lane = threadIdx.x & 31;
    const int t = s >> 4, b = s & 15;
    const size_t base0 = (size_t)s * HID;
    const size_t base1 = (size_t)(32768 + s) * HID;

    float z0 = 0.f, z1 = 0.f;
#pragma unroll
    for (int i = 0; i < 8; i++) {
        int c = lane + 32 * i;
        float h0 = g_hs[base0 + c];
        float h1 = g_hs[base1 + c];
        z0 += g_wf[c] * h0 + g_wf[256 + c] * h1;
        z1 += g_wf[512 + c] * h0 + g_wf[768 + c] * h1;
    }
#pragma unroll
    for (int o = 16; o > 0; o >>= 1) {
        z0 += __shfl_xor_sync(0xffffffffu, z0, o);
        z1 += __shfl_xor_sync(0xffffffffu, z1, o);
    }
    if (lane == 0) {
        float a0 = (z0 + g_zc[0]) * 0.1f;
        float a1 = (z1 + g_zc[1]) * 0.1f;
        float m = fmaxf(a0, a1);
        float e0 = __expf(a0 - m), e1 = __expf(a1 - m);
        float inv = 1.f / (e0 + e1);
        size_t po = ((size_t)b * T_LEN + t) * 2;
        out[po]     = e0 * inv;
        out[po + 1] = e1 * inv;
        float u0 = u[po], u1 = u[po + 1];
        float gg0 = -logf(-logf(u0 + 1e-20f) + 1e-20f);
        float gg1 = -logf(-logf(u1 + 1e-20f) + 1e-20f);
        int ind = (a1 + gg1 > a0 + gg0) ? 1 : 0;
        g_sampled[b * T_LEN + t] = ind ? e[b * T_LEN + t] : 0.f;
    }
}

// ============================================================================
// K5: three successive median-5 pools with reflect padding, one CTA per batch.
// ============================================================================
__device__ __forceinline__ float median5_(float v0, float v1, float v2,
                                          float v3, float v4) {
#define CSWP(a, b) { float _t = fminf(a, b); b = fmaxf(a, b); a = _t; }
    CSWP(v0, v1); CSWP(v1, v2); CSWP(v2, v3); CSWP(v3, v4);
    CSWP(v0, v1); CSWP(v1, v2); CSWP(v2, v3);
    CSWP(v0, v1); CSWP(v1, v2);
#undef CSWP
    return v2;
}

__global__ void medpool_k(float* __restrict__ out) {
    __shared__ float bufA[2048], bufB[2048];
    const int b = blockIdx.x, tid = threadIdx.x;
    for (int i = tid; i < 2048; i += 256) bufA[i] = g_sampled[b * 2048 + i];
    __syncthreads();
    float* src = bufA;
    float* dst = bufB;
    for (int pass = 0; pass < 3; pass++) {
        for (int i = tid; i < 2048; i += 256) {
            float v[5];
#pragma unroll
            for (int jj = 0; jj < 5; jj++) {
                int j = i + jj - 2;
                j = (j < 0) ? -j : ((j > 2047) ? (4094 - j) : j);
                v[jj] = src[j];
            }
            dst[i] = median5_(v[0], v[1], v[2], v[3], v[4]);
        }
        __syncthreads();
        float* tmp = src; src = dst; dst = tmp;
    }
    for (int i = tid; i < 2048; i += 256)
        out[65536 + b * 2048 + i] = src[i];
}

// ============================================================================
extern "C" void kernel_launch(void* const* d_in, const int* in_sizes, int n_in,
                              void* d_out, int out_size) {
    const float* x      = (const float*)d_in[0];
    const float* e      = (const float*)d_in[1];
    const float* u      = (const float*)d_in[2];
    const float* Wih_f  = (const float*)d_in[3];
    const float* Whh_f  = (const float*)d_in[4];
    const float* bih_f  = (const float*)d_in[5];
    const float* bhh_f  = (const float*)d_in[6];
    const float* Wih_b  = (const float*)d_in[7];
    const float* Whh_b  = (const float*)d_in[8];
    const float* bih_b  = (const float*)d_in[9];
    const float* bhh_b  = (const float*)d_in[10];
    const float* gamma  = (const float*)d_in[11];
    const float* beta   = (const float*)d_in[12];
    const float* Wlin   = (const float*)d_in[13];
    const float* blin   = (const float*)d_in[14];
    float* out = (float*)d_out;

    cudaFuncSetAttribute(lstm_k, cudaFuncAttributeMaxDynamicSharedMemorySize,
                         LSTM_SMEM);

    dim3 gg(32, 256);
    gemm_proj<<<gg, 256>>>(x, Wih_f, Wih_b);
    lstm_k<<<128, 512, LSTM_SMEM>>>(Whh_f, Whh_b, bih_f, bhh_f, bih_b, bhh_b);
    bn_part<<<128, 512>>>();
    bn_final<<<1, 512>>>(gamma, beta, Wlin, blin);
    post_k<<<4096, 256>>>(u, e, out);
    medpool_k<<<16, 256>>>(out);
}

// round 5
// speedup vs baseline: 1.1653x; 1.1653x over previous
#include <cuda_runtime.h>
#include <cuda_bf16.h>
#include <cstdint>
#include <cstddef>

#define T_LEN 2048
#define BATCH 16
#define HID   256
#define CIN   512
#define GATES 1024              // 4*H per direction
#define NCOL  2048              // gates for both directions
#define MROWS (BATCH * T_LEN)   // 32768

// ---------------- scratch (static device globals; no allocations) ----------
__device__ float g_proj[(size_t)MROWS * NCOL];            // 256 MB: input projection
__device__ float g_hs[(size_t)2 * T_LEN * BATCH * HID];   // 64 MB: h outputs [dir][t][b][c]
__device__ float g_part[128 * 512 * 2];                   // BN partial sums
__device__ float g_wf[4 * 512];                           // folded Wlin
__device__ float g_zc[2];                                 // folded bias
__device__ float g_sampled[BATCH * T_LEN];                // sampled pre-median
__device__ __align__(16) __nv_bfloat16 g_xt[(size_t)BATCH * T_LEN * CIN]; // x^T bf16 [b][t][k]
__device__ __align__(16) __nv_bfloat16 g_wc[(size_t)NCOL * CIN];          // W bf16 [n][k]

// ===================== PTX helpers (compute_103-safe only) ==================
__device__ __forceinline__ uint32_t smem_u32(const void* p) {
    return (uint32_t)__cvta_generic_to_shared(p);
}
__device__ __forceinline__ void cp_async16(uint32_t saddr, const void* g) {
    asm volatile("cp.async.cg.shared.global [%0], [%1], 16;"
                 :: "r"(saddr), "l"(g) : "memory");
}
__device__ __forceinline__ void ldsm_x4(uint32_t* r, uint32_t saddr) {
    asm volatile("ldmatrix.sync.aligned.m8n8.x4.shared.b16 {%0,%1,%2,%3}, [%4];"
                 : "=r"(r[0]), "=r"(r[1]), "=r"(r[2]), "=r"(r[3]) : "r"(saddr));
}
__device__ __forceinline__ void mma16816(float* c, const uint32_t* a, const uint32_t* b) {
    asm volatile("mma.sync.aligned.m16n8k16.row.col.f32.bf16.bf16.f32 "
                 "{%0,%1,%2,%3}, {%4,%5,%6,%7}, {%8,%9}, {%0,%1,%2,%3};"
                 : "+f"(c[0]), "+f"(c[1]), "+f"(c[2]), "+f"(c[3])
                 : "r"(a[0]), "r"(a[1]), "r"(a[2]), "r"(a[3]), "r"(b[0]), "r"(b[1]));
}

// ============================================================================
// K0a: transpose+convert x[b][k][t] fp32 -> g_xt[b][t][k] bf16
// ============================================================================
__global__ void conv_x(const float* __restrict__ X) {
    __shared__ float tile[32][33];
    const int b = blockIdx.z;
    const int k0 = blockIdx.y * 32;
    const int t0 = blockIdx.x * 32;
    const int tx = threadIdx.x, ty = threadIdx.y;   // 32 x 8
#pragma unroll
    for (int i = ty; i < 32; i += 8)
        tile[i][tx] = X[((size_t)b * CIN + k0 + i) * T_LEN + t0 + tx];
    __syncthreads();
#pragma unroll
    for (int i = ty; i < 32; i += 8)
        g_xt[((size_t)b * T_LEN + t0 + i) * CIN + k0 + tx] =
            __float2bfloat16(tile[tx][i]);
}

// K0b: convert W rows -> g_wc bf16 [2048][512] (f rows then b rows)
__global__ void conv_w(const float* __restrict__ Wf, const float* __restrict__ Wb) {
    size_t i = (size_t)blockIdx.x * 256 + threadIdx.x;   // < 1048576
    const size_t half = (size_t)GATES * CIN;
    if (i < half) g_wc[i] = __float2bfloat16(Wf[i]);
    else          g_wc[i] = __float2bfloat16(Wb[i - half]);
}

// ============================================================================
// K1: bf16 TN GEMM via ldmatrix + mma.sync (m16n8k16).
// CTA tile 128(M) x 128(N), K staged 64 at a time. 8 warps, 32x64 per warp.
// smem rows padded to 72 bf16 (144B) -> ldmatrix rows hit distinct bank groups.
// ============================================================================
#define ASTR 72                       // bf16 elements per smem row
#define A_BYTES (128 * ASTR * 2)      // 18432

__global__ void __launch_bounds__(256) gemm_tc() {
    __shared__ __align__(16) char smraw[2 * A_BYTES];
    const uint32_t sb = smem_u32(smraw);
    const uint32_t A_OFF = 0, B_OFF = A_BYTES;

    const int tid = threadIdx.x;
    const int wid = tid >> 5, lane = tid & 31;
    const int wm = wid >> 1;              // 0..3 -> 32-row slice
    const int wn = wid & 1;               // 0..1 -> 64-col slice
    const int nt = blockIdx.x;            // 0..15
    const int mt = blockIdx.y;            // 0..255
    const int m0 = mt * 128;
    const int bq = m0 >> 11, t0 = m0 & 2047;   // tiles never straddle batch

    float acc[2][8][4];
#pragma unroll
    for (int i = 0; i < 2; i++)
#pragma unroll
        for (int j = 0; j < 8; j++)
#pragma unroll
            for (int q = 0; q < 4; q++) acc[i][j][q] = 0.f;

    // precomputed ldmatrix lane addressing
    const int a_row = lane & 15, a_koff = (lane >> 4) * 8;
    const int b_nrow = (lane & 7) + ((lane >> 4) << 3);
    const int b_koff = ((lane >> 3) & 1) * 8;

    for (int kc = 0; kc < 8; kc++) {        // K = 8 x 64
        __syncthreads();                    // previous compute done
        // FULL row fill: 128 rows x 8 segs x 16B for A and B (1024 each)
#pragma unroll
        for (int i = 0; i < 4; i++) {
            int idx = tid + i * 256;        // 0..1023
            int row = idx >> 3, seg = idx & 7;
            cp_async16(sb + A_OFF + (uint32_t)(row * ASTR + seg * 8) * 2,
                       &g_xt[((size_t)bq * T_LEN + t0 + row) * CIN + kc * 64 + seg * 8]);
            cp_async16(sb + B_OFF + (uint32_t)(row * ASTR + seg * 8) * 2,
                       &g_wc[((size_t)(nt * 128 + row)) * CIN + kc * 64 + seg * 8]);
        }
        asm volatile("cp.async.commit_group;" ::: "memory");
        asm volatile("cp.async.wait_group 0;" ::: "memory");
        __syncthreads();

#pragma unroll
        for (int ks = 0; ks < 4; ks++) {    // 4 x k16
            uint32_t afr[2][4];
#pragma unroll
            for (int m2 = 0; m2 < 2; m2++)
                ldsm_x4(afr[m2],
                        sb + A_OFF +
                        (uint32_t)((wm * 32 + m2 * 16 + a_row) * ASTR +
                                   ks * 16 + a_koff) * 2);
            uint32_t bfr[8][2];
#pragma unroll
            for (int p = 0; p < 4; p++) {
                uint32_t r[4];
                ldsm_x4(r, sb + B_OFF +
                           (uint32_t)((wn * 64 + p * 16 + b_nrow) * ASTR +
                                      ks * 16 + b_koff) * 2);
                bfr[p * 2][0] = r[0]; bfr[p * 2][1] = r[1];
                bfr[p * 2 + 1][0] = r[2]; bfr[p * 2 + 1][1] = r[3];
            }
#pragma unroll
            for (int m2 = 0; m2 < 2; m2++)
#pragma unroll
                for (int n8 = 0; n8 < 8; n8++)
                    mma16816(acc[m2][n8], afr[m2], bfr[n8]);
        }
    }

    // epilogue: c frag (t/4 = row, (t%4)*2 = col)
#pragma unroll
    for (int m2 = 0; m2 < 2; m2++)
#pragma unroll
        for (int hf = 0; hf < 2; hf++) {
            int row = m0 + wm * 32 + m2 * 16 + hf * 8 + (lane >> 2);
            float* dst = &g_proj[(size_t)row * NCOL + nt * 128 + wn * 64 + (lane & 3) * 2];
#pragma unroll
            for (int n8 = 0; n8 < 8; n8++) {
                float2 v = make_float2(acc[m2][n8][hf * 2], acc[m2][n8][hf * 2 + 1]);
                *(float2*)(dst + n8 * 8) = v;
            }
        }
}

// ============================================================================
// K2: LSTM recurrence. 32 chains (dir,b) x 4-CTA clusters; 64 cells/CTA.
// Whh slice in smem as bf16 (128KB). Proj prefetched one step ahead.
// ============================================================================
__device__ __forceinline__ void cluster_sync_() {
    asm volatile("barrier.cluster.arrive.aligned;" ::: "memory");
    asm volatile("barrier.cluster.wait.aligned;" ::: "memory");
}
__device__ __forceinline__ float sigm_(float x) { return 1.f / (1.f + __expf(-x)); }

#define LSTM_SMEM (131072 + 2048 + 1024 + 256 + 1024)

__global__ void __cluster_dims__(4, 1, 1) lstm_k(
    const float* __restrict__ WhhF, const float* __restrict__ WhhB,
    const float* __restrict__ bihF, const float* __restrict__ bhhF,
    const float* __restrict__ bihB, const float* __restrict__ bhhB) {
    extern __shared__ char smem[];
    __nv_bfloat16* w = (__nv_bfloat16*)smem;              // [256][256] bf16
    float* hbuf  = (float*)(smem + 131072);               // [2][256]
    float* gates = hbuf + 512;                            // [256]
    float* cst   = gates + 256;                           // [64]
    float* bias  = cst + 64;                              // [256]

    const int tid = threadIdx.x;                          // 512 threads
    const int cbid = blockIdx.x;
    const int chain = cbid >> 2;                          // 0..31
    const int r = cbid & 3;                               // rank in cluster
    const int dir = chain >> 4;
    const int b = chain & 15;

    const float* Whh = dir ? WhhB : WhhF;
    const float* bih = dir ? bihB : bihF;
    const float* bhh = dir ? bhhB : bhhF;

    for (int idx = tid; idx < 256 * 256; idx += 512) {
        int q = idx >> 8, k = idx & 255;
        int grow = ((q >> 6) << 8) + (r << 6) + (q & 63);
        w[idx] = __float2bfloat16(Whh[(size_t)grow * HID + k]);
    }
    if (tid < 256) {
        int grow = ((tid >> 6) << 8) + (r << 6) + (tid & 63);
        bias[tid] = bih[grow] + bhh[grow];
        hbuf[tid] = 0.f;
        hbuf[256 + tid] = 0.f;
    }
    if (tid < 64) cst[tid] = 0.f;
    __syncthreads();
    cluster_sync_();

    const int g  = tid >> 1;
    const int kh = (tid & 1) << 7;   // 0 or 128
    const int grow_g = ((g >> 6) << 8) + (r << 6) + (g & 63);
    const uint4* wrow = (const uint4*)(w + (size_t)g * 256 + kh);
    const size_t proj_col = (size_t)dir * GATES + grow_g;
    const bool even = (tid & 1) == 0;

    float pv = 0.f;
    {
        int te0 = dir ? (T_LEN - 1) : 0;
        if (even) pv = g_proj[(size_t)(b * T_LEN + te0) * NCOL + proj_col];
    }

    int p = 0;
    for (int step = 0; step < T_LEN; step++) {
        const int te = dir ? (T_LEN - 1 - step) : step;
        const float4* hv = (const float4*)(hbuf + p * 256 + kh);

        float acc0 = 0.f, acc1 = 0.f;
#pragma unroll
        for (int c = 0; c < 16; c += 2) {
            uint4 wp = wrow[c];
            float4 h0 = hv[c * 2];
            float4 h1 = hv[c * 2 + 1];
            acc0 += __uint_as_float(wp.x << 16) * h0.x;
            acc0 += __uint_as_float(wp.x & 0xffff0000u) * h0.y;
            acc0 += __uint_as_float(wp.y << 16) * h0.z;
            acc0 += __uint_as_float(wp.y & 0xffff0000u) * h0.w;
            acc0 += __uint_as_float(wp.z << 16) * h1.x;
            acc0 += __uint_as_float(wp.z & 0xffff0000u) * h1.y;
            acc0 += __uint_as_float(wp.w << 16) * h1.z;
            acc0 += __uint_as_float(wp.w & 0xffff0000u) * h1.w;
            uint4 wq = wrow[c + 1];
            float4 h2 = hv[c * 2 + 2];
            float4 h3 = hv[c * 2 + 3];
            acc1 += __uint_as_float(wq.x << 16) * h2.x;
            acc1 += __uint_as_float(wq.x & 0xffff0000u) * h2.y;
            acc1 += __uint_as_float(wq.y << 16) * h2.z;
            acc1 += __uint_as_float(wq.y & 0xffff0000u) * h2.w;
            acc1 += __uint_as_float(wq.z << 16) * h3.x;
            acc1 += __uint_as_float(wq.z & 0xffff0000u) * h3.y;
            acc1 += __uint_as_float(wq.w << 16) * h3.z;
            acc1 += __uint_as_float(wq.w & 0xffff0000u) * h3.w;
        }
        float acc = acc0 + acc1;
        acc += __shfl_xor_sync(0xffffffffu, acc, 1);
        if (even) gates[g] = acc + bias[g] + pv;

        if (even && step + 1 < T_LEN) {
            int tn = dir ? (T_LEN - 2 - step) : (step + 1);
            pv = g_proj[(size_t)(b * T_LEN + tn) * NCOL + proj_col];
        }
        __syncthreads();

        if (tid < 64) {
            float iv = sigm_(gates[tid]);
            float fv = sigm_(gates[64 + tid]);
            float gv = tanhf(gates[128 + tid]);
            float ov = sigm_(gates[192 + tid]);
            float c = fv * cst[tid] + iv * gv;
            cst[tid] = c;
            float hval = ov * tanhf(c);
            g_hs[(size_t)((dir * T_LEN + te) * BATCH + b) * HID + r * 64 + tid] = hval;

            int np = p ^ 1;
            float* dst = hbuf + np * 256 + r * 64 + tid;
            *dst = hval;
            uint32_t la = (uint32_t)__cvta_generic_to_shared(dst);
#pragma unroll
            for (int pc = 0; pc < 4; pc++) {
                if (pc == r) continue;
                uint32_t ra;
                asm("mapa.shared::cluster.u32 %0, %1, %2;" : "=r"(ra) : "r"(la), "r"(pc));
                asm volatile("st.shared::cluster.f32 [%0], %1;" :: "r"(ra), "f"(hval)
                             : "memory");
            }
        }
        cluster_sync_();
        p ^= 1;
    }
}

// ============================================================================
// K3a/K3b: BN stats + fold into Linear
// ============================================================================
__global__ void bn_part() {
    const int ch = threadIdx.x;
    const int dir = ch >> 8, cc = ch & 255;
    const int s0 = blockIdx.x * 256;
    float sum = 0.f, sq = 0.f;
    const size_t base = (size_t)dir * T_LEN * BATCH * HID + cc;
#pragma unroll 4
    for (int i = 0; i < 256; i++) {
        float v = g_hs[base + (size_t)(s0 + i) * HID];
        sum += v; sq += v * v;
    }
    g_part[((size_t)blockIdx.x * 512 + ch) * 2]     = sum;
    g_part[((size_t)blockIdx.x * 512 + ch) * 2 + 1] = sq;
}

__global__ void bn_final(const float* __restrict__ gamma,
                         const float* __restrict__ beta,
                         const float* __restrict__ Wlin,
                         const float* __restrict__ blin) {
    __shared__ float red[512];
    const int ch = threadIdx.x;
    double s = 0.0, q = 0.0;
#pragma unroll 8
    for (int i = 0; i < 128; i++) {
        s += (double)g_part[((size_t)i * 512 + ch) * 2];
        q += (double)g_part[((size_t)i * 512 + ch) * 2 + 1];
    }
    const double n = 32768.0;
    float mean = (float)(s / n);
    float var  = (float)(q / n - (s / n) * (s / n));
    float A  = gamma[ch] * rsqrtf(var + 1e-5f);
    float Bc = beta[ch] - mean * A;

    g_wf[ch]       = Wlin[ch] * A;
    g_wf[512 + ch] = Wlin[512 + ch] * A;

    red[ch] = Wlin[ch] * Bc;
    __syncthreads();
    for (int o = 256; o > 0; o >>= 1) {
        if (ch < o) red[ch] += red[ch + o];
        __syncthreads();
    }
    if (ch == 0) g_zc[0] = blin[0] + red[0];
    __syncthreads();
    red[ch] = Wlin[512 + ch] * Bc;
    __syncthreads();
    for (int o = 256; o > 0; o >>= 1) {
        if (ch < o) red[ch] += red[ch + o];
        __syncthreads();
    }
    if (ch == 0) g_zc[1] = blin[1] + red[0];
}

// ============================================================================
// K4: posterior + gumbel argmax + sampled
// ============================================================================
__global__ void post_k(const float* __restrict__ u,
                       const float* __restrict__ e,
                       float* __restrict__ out) {
    const int s = blockIdx.x * 8 + (threadIdx.x >> 5);
    const int lane = threadIdx.x & 31;
    const int t = s >> 4, b = s & 15;
    const size_t base0 = (size_t)s * HID;
    const size_t base1 = (size_t)(32768 + s) * HID;

    float z0 = 0.f, z1 = 0.f;
#pragma unroll
    for (int i = 0; i < 8; i++) {
        int c = lane + 32 * i;
        float h0 = g_hs[base0 + c];
        float h1 = g_hs[base1 + c];
        z0 += g_wf[c] * h0 + g_wf[256 + c] * h1;
        z1 += g_wf[512 + c] * h0 + g_wf[768 + c] * h1;
    }
#pragma unroll
    for (int o = 16; o > 0; o >>= 1) {
        z0 += __shfl_xor_sync(0xffffffffu, z0, o);
        z1 += __shfl_xor_sync(0xffffffffu, z1, o);
    }
    if (lane == 0) {
        float a0 = (z0 + g_zc[0]) * 0.1f;
        float a1 = (z1 + g_zc[1]) * 0.1f;
        float m = fmaxf(a0, a1);
        float e0 = __expf(a0 - m), e1 = __expf(a1 - m);
        float inv = 1.f / (e0 + e1);
        size_t po = ((size_t)b * T_LEN + t) * 2;
        out[po]     = e0 * inv;
        out[po + 1] = e1 * inv;
        float u0 = u[po], u1 = u[po + 1];
        float gg0 = -logf(-logf(u0 + 1e-20f) + 1e-20f);
        float gg1 = -logf(-logf(u1 + 1e-20f) + 1e-20f);
        int ind = (a1 + gg1 > a0 + gg0) ? 1 : 0;
        g_sampled[b * T_LEN + t] = ind ? e[b * T_LEN + t] : 0.f;
    }
}

// ============================================================================
// K5: three successive median-5 pools
// ============================================================================
__device__ __forceinline__ float median5_(float v0, float v1, float v2,
                                          float v3, float v4) {
#define CSWP(a, b) { float _t = fminf(a, b); b = fmaxf(a, b); a = _t; }
    CSWP(v0, v1); CSWP(v1, v2); CSWP(v2, v3); CSWP(v3, v4);
    CSWP(v0, v1); CSWP(v1, v2); CSWP(v2, v3);
    CSWP(v0, v1); CSWP(v1, v2);
#undef CSWP
    return v2;
}

__global__ void medpool_k(float* __restrict__ out) {
    __shared__ float bufA[2048], bufB[2048];
    const int b = blockIdx.x, tid = threadIdx.x;
    for (int i = tid; i < 2048; i += 256) bufA[i] = g_sampled[b * 2048 + i];
    __syncthreads();
    float* src = bufA;
    float* dst = bufB;
    for (int pass = 0; pass < 3; pass++) {
        for (int i = tid; i < 2048; i += 256) {
            float v[5];
#pragma unroll
            for (int jj = 0; jj < 5; jj++) {
                int j = i + jj - 2;
                j = (j < 0) ? -j : ((j > 2047) ? (4094 - j) : j);
                v[jj] = src[j];
            }
            dst[i] = median5_(v[0], v[1], v[2], v[3], v[4]);
        }
        __syncthreads();
        float* tmp = src; src = dst; dst = tmp;
    }
    for (int i = tid; i < 2048; i += 256)
        out[65536 + b * 2048 + i] = src[i];
}

// ============================================================================
extern "C" void kernel_launch(void* const* d_in, const int* in_sizes, int n_in,
                              void* d_out, int out_size) {
    const float* x      = (const float*)d_in[0];
    const float* e      = (const float*)d_in[1];
    const float* u      = (const float*)d_in[2];
    const float* Wih_f  = (const float*)d_in[3];
    const float* Whh_f  = (const float*)d_in[4];
    const float* bih_f  = (const float*)d_in[5];
    const float* bhh_f  = (const float*)d_in[6];
    const float* Wih_b  = (const float*)d_in[7];
    const float* Whh_b  = (const float*)d_in[8];
    const float* bih_b  = (const float*)d_in[9];
    const float* bhh_b  = (const float*)d_in[10];
    const float* gamma  = (const float*)d_in[11];
    const float* beta   = (const float*)d_in[12];
    const float* Wlin   = (const float*)d_in[13];
    const float* blin   = (const float*)d_in[14];
    float* out = (float*)d_out;

    cudaFuncSetAttribute(lstm_k, cudaFuncAttributeMaxDynamicSharedMemorySize,
                         LSTM_SMEM);

    conv_x<<<dim3(64, 16, 16), dim3(32, 8)>>>(x);
    conv_w<<<4096, 256>>>(Wih_f, Wih_b);
    gemm_tc<<<dim3(16, 256), 256>>>();
    lstm_k<<<128, 512, LSTM_SMEM>>>(Whh_f, Whh_b, bih_f, bhh_f, bih_b, bhh_b);
    bn_part<<<128, 512>>>();
    bn_final<<<1, 512>>>(gamma, beta, Wlin, blin);
    post_k<<<4096, 256>>>(u, e, out);
    medpool_k<<<16, 256>>>(out);
}

// round 6
// speedup vs baseline: 2.5709x; 2.2063x over previous
#include <cuda_runtime.h>
#include <cuda_bf16.h>
#include <cstdint>
#include <cstddef>

#define T_LEN 2048
#define BATCH 16
#define HID   256
#define CIN   512
#define GATES 1024              // 4*H per direction
#define NCOL  2048              // gates for both directions
#define MROWS (BATCH * T_LEN)   // 32768

// ---------------- scratch (static device globals; no allocations) ----------
__device__ float g_proj[(size_t)MROWS * NCOL];            // 256 MB: input projection
__device__ float g_hs[(size_t)2 * T_LEN * BATCH * HID];   // 64 MB: h outputs [dir][t][b][c]
__device__ float g_part[128 * 512 * 2];                   // BN partial sums
__device__ float g_wf[4 * 512];                           // folded Wlin
__device__ float g_zc[2];                                 // folded bias
__device__ float g_sampled[BATCH * T_LEN];                // sampled pre-median
__device__ __align__(16) __nv_bfloat16 g_xt[(size_t)BATCH * T_LEN * CIN]; // x^T bf16 [b][t][k]
__device__ __align__(16) __nv_bfloat16 g_wc[(size_t)NCOL * CIN];          // W bf16 [n][k]

// ===================== PTX helpers (compute_103-safe only) ==================
__device__ __forceinline__ uint32_t smem_u32(const void* p) {
    return (uint32_t)__cvta_generic_to_shared(p);
}
__device__ __forceinline__ void cp_async16(uint32_t saddr, const void* g) {
    asm volatile("cp.async.cg.shared.global [%0], [%1], 16;"
                 :: "r"(saddr), "l"(g) : "memory");
}
__device__ __forceinline__ void ldsm_x4(uint32_t* r, uint32_t saddr) {
    asm volatile("ldmatrix.sync.aligned.m8n8.x4.shared.b16 {%0,%1,%2,%3}, [%4];"
                 : "=r"(r[0]), "=r"(r[1]), "=r"(r[2]), "=r"(r[3]) : "r"(saddr));
}
__device__ __forceinline__ void mma16816(float* c, const uint32_t* a, const uint32_t* b) {
    asm volatile("mma.sync.aligned.m16n8k16.row.col.f32.bf16.bf16.f32 "
                 "{%0,%1,%2,%3}, {%4,%5,%6,%7}, {%8,%9}, {%0,%1,%2,%3};"
                 : "+f"(c[0]), "+f"(c[1]), "+f"(c[2]), "+f"(c[3])
                 : "r"(a[0]), "r"(a[1]), "r"(a[2]), "r"(a[3]), "r"(b[0]), "r"(b[1]));
}

// ============================================================================
// K0a: transpose+convert x[b][k][t] fp32 -> g_xt[b][t][k] bf16
// ============================================================================
__global__ void conv_x(const float* __restrict__ X) {
    __shared__ float tile[32][33];
    const int b = blockIdx.z;
    const int k0 = blockIdx.y * 32;
    const int t0 = blockIdx.x * 32;
    const int tx = threadIdx.x, ty = threadIdx.y;   // 32 x 8
#pragma unroll
    for (int i = ty; i < 32; i += 8)
        tile[i][tx] = X[((size_t)b * CIN + k0 + i) * T_LEN + t0 + tx];
    __syncthreads();
#pragma unroll
    for (int i = ty; i < 32; i += 8)
        g_xt[((size_t)b * T_LEN + t0 + i) * CIN + k0 + tx] =
            __float2bfloat16(tile[tx][i]);
}

// K0b: convert W rows -> g_wc bf16 [2048][512] (f rows then b rows)
__global__ void conv_w(const float* __restrict__ Wf, const float* __restrict__ Wb) {
    size_t i = (size_t)blockIdx.x * 256 + threadIdx.x;   // < 1048576
    const size_t half = (size_t)GATES * CIN;
    if (i < half) g_wc[i] = __float2bfloat16(Wf[i]);
    else          g_wc[i] = __float2bfloat16(Wb[i - half]);
}

// ============================================================================
// K1: bf16 TN GEMM via ldmatrix + mma.sync (m16n8k16).
// CTA tile 128(M) x 128(N), K staged 64 at a time. 8 warps, 32x64 per warp.
// ============================================================================
#define ASTR 72                       // bf16 elements per smem row
#define A_BYTES (128 * ASTR * 2)      // 18432

__global__ void __launch_bounds__(256) gemm_tc() {
    __shared__ __align__(16) char smraw[2 * A_BYTES];
    const uint32_t sb = smem_u32(smraw);
    const uint32_t A_OFF = 0, B_OFF = A_BYTES;

    const int tid = threadIdx.x;
    const int wid = tid >> 5, lane = tid & 31;
    const int wm = wid >> 1;              // 0..3 -> 32-row slice
    const int wn = wid & 1;               // 0..1 -> 64-col slice
    const int nt = blockIdx.x;            // 0..15
    const int mt = blockIdx.y;            // 0..255
    const int m0 = mt * 128;
    const int bq = m0 >> 11, t0 = m0 & 2047;

    float acc[2][8][4];
#pragma unroll
    for (int i = 0; i < 2; i++)
#pragma unroll
        for (int j = 0; j < 8; j++)
#pragma unroll
            for (int q = 0; q < 4; q++) acc[i][j][q] = 0.f;

    const int a_row = lane & 15, a_koff = (lane >> 4) * 8;
    const int b_nrow = (lane & 7) + ((lane >> 4) << 3);
    const int b_koff = ((lane >> 3) & 1) * 8;

    for (int kc = 0; kc < 8; kc++) {        // K = 8 x 64
        __syncthreads();
#pragma unroll
        for (int i = 0; i < 4; i++) {
            int idx = tid + i * 256;        // 0..1023
            int row = idx >> 3, seg = idx & 7;
            cp_async16(sb + A_OFF + (uint32_t)(row * ASTR + seg * 8) * 2,
                       &g_xt[((size_t)bq * T_LEN + t0 + row) * CIN + kc * 64 + seg * 8]);
            cp_async16(sb + B_OFF + (uint32_t)(row * ASTR + seg * 8) * 2,
                       &g_wc[((size_t)(nt * 128 + row)) * CIN + kc * 64 + seg * 8]);
        }
        asm volatile("cp.async.commit_group;" ::: "memory");
        asm volatile("cp.async.wait_group 0;" ::: "memory");
        __syncthreads();

#pragma unroll
        for (int ks = 0; ks < 4; ks++) {
            uint32_t afr[2][4];
#pragma unroll
            for (int m2 = 0; m2 < 2; m2++)
                ldsm_x4(afr[m2],
                        sb + A_OFF +
                        (uint32_t)((wm * 32 + m2 * 16 + a_row) * ASTR +
                                   ks * 16 + a_koff) * 2);
            uint32_t bfr[8][2];
#pragma unroll
            for (int p = 0; p < 4; p++) {
                uint32_t r[4];
                ldsm_x4(r, sb + B_OFF +
                           (uint32_t)((wn * 64 + p * 16 + b_nrow) * ASTR +
                                      ks * 16 + b_koff) * 2);
                bfr[p * 2][0] = r[0]; bfr[p * 2][1] = r[1];
                bfr[p * 2 + 1][0] = r[2]; bfr[p * 2 + 1][1] = r[3];
            }
#pragma unroll
            for (int m2 = 0; m2 < 2; m2++)
#pragma unroll
                for (int n8 = 0; n8 < 8; n8++)
                    mma16816(acc[m2][n8], afr[m2], bfr[n8]);
        }
    }

#pragma unroll
    for (int m2 = 0; m2 < 2; m2++)
#pragma unroll
        for (int hf = 0; hf < 2; hf++) {
            int row = m0 + wm * 32 + m2 * 16 + hf * 8 + (lane >> 2);
            float* dst = &g_proj[(size_t)row * NCOL + nt * 128 + wn * 64 + (lane & 3) * 2];
#pragma unroll
            for (int n8 = 0; n8 < 8; n8++) {
                float2 v = make_float2(acc[m2][n8][hf * 2], acc[m2][n8][hf * 2 + 1]);
                *(float2*)(dst + n8 * 8) = v;
            }
        }
}

// ============================================================================
// K2: LSTM recurrence, v2. 32 chains x 4-CTA clusters; 64 cells/CTA.
// Weights in REGISTERS (no smem weight reads -> no bank conflicts).
// Thread = 4 gate-rows x 32-k slice; 8-lane shfl reduction per row.
// h in smem with padded k-chunk layout (stride 36 words, conflict-free).
// ============================================================================
__device__ __forceinline__ void cluster_sync_() {
    asm volatile("barrier.cluster.arrive.aligned;" ::: "memory");
    asm volatile("barrier.cluster.wait.aligned;" ::: "memory");
}
__device__ __forceinline__ float sigm_(float x) { return 1.f / (1.f + __expf(-x)); }
__device__ __forceinline__ float tanh_(float x) {
    x = fminf(fmaxf(x, -15.f), 15.f);
    float e = __expf(2.f * x);
    return (e - 1.f) / (e + 1.f);
}

#define HSTR 36                      // padded words per 32-float k-chunk
#define HBUF (8 * HSTR)              // 288 words per buffer

__global__ void __cluster_dims__(4, 1, 1) __launch_bounds__(512, 1) lstm_k(
    const float* __restrict__ WhhF, const float* __restrict__ WhhB,
    const float* __restrict__ bihF, const float* __restrict__ bhhF,
    const float* __restrict__ bihB, const float* __restrict__ bhhB) {
    __shared__ float hbuf[2 * HBUF];
    __shared__ float gates[256];
    __shared__ float bias[256];

    const int tid = threadIdx.x;                          // 512 threads
    const int cbid = blockIdx.x;
    const int chain = cbid >> 2;                          // 0..31
    const int r = cbid & 3;                               // rank in cluster
    const int dir = chain >> 4;
    const int b = chain & 15;

    const float* Whh = dir ? WhhB : WhhF;
    const float* bih = dir ? bihB : bihF;
    const float* bhh = dir ? bhhB : bhhF;

    const int wrp = tid >> 5, lane = tid & 31;
    const int ks = lane & 7;             // k-slice: k in [ks*32, ks*32+32)
    const int rg = lane >> 3;            // row group 0..3
    const int lr0 = wrp * 16 + rg * 4;   // first of this thread's 4 local rows

    // weights -> registers: 4 rows x 32 k, packed bf16 pairs
    uint32_t wreg[4][16];
#pragma unroll
    for (int r4 = 0; r4 < 4; r4++) {
        int lr = lr0 + r4;
        int grow = ((lr >> 6) << 8) + (r << 6) + (lr & 63);
        const float* wr = Whh + (size_t)grow * HID + ks * 32;
#pragma unroll
        for (int j = 0; j < 16; j++) {
            float2 f2 = *(const float2*)(wr + 2 * j);
            wreg[r4][j] =
                (uint32_t)__bfloat16_as_ushort(__float2bfloat16(f2.x)) |
                ((uint32_t)__bfloat16_as_ushort(__float2bfloat16(f2.y)) << 16);
        }
    }

    if (tid < 256) {
        int grow = ((tid >> 6) << 8) + (r << 6) + (tid & 63);
        bias[tid] = bih[grow] + bhh[grow];
    }
    if (tid < HBUF) { hbuf[tid] = 0.f; hbuf[HBUF + tid] = 0.f; }

    float creg = 0.f;                    // cell state (tid < 64 uses it)

    // proj prefetch (ks==0 lanes own rows lr0..lr0+3 -> 4 consecutive cols)
    const int grow0 = ((lr0 >> 6) << 8) + (r << 6) + (lr0 & 63);
    const size_t pcol = (size_t)dir * GATES + grow0;
    float4 pv = make_float4(0.f, 0.f, 0.f, 0.f);
    if (ks == 0) {
        int te0 = dir ? (T_LEN - 1) : 0;
        pv = *(const float4*)&g_proj[(size_t)(b * T_LEN + te0) * NCOL + pcol];
    }

    __syncthreads();
    cluster_sync_();

    int p = 0;
    for (int step = 0; step < T_LEN; step++) {
        const int te = dir ? (T_LEN - 1 - step) : step;
        const float* hb = hbuf + p * HBUF + ks * HSTR;

        float a0 = 0.f, a1 = 0.f, a2 = 0.f, a3 = 0.f;
#pragma unroll
        for (int j = 0; j < 8; j++) {
            float4 h4 = *(const float4*)(hb + j * 4);
            {
                uint32_t u0 = wreg[0][2 * j], u1 = wreg[0][2 * j + 1];
                a0 += __uint_as_float(u0 << 16) * h4.x;
                a0 += __uint_as_float(u0 & 0xffff0000u) * h4.y;
                a0 += __uint_as_float(u1 << 16) * h4.z;
                a0 += __uint_as_float(u1 & 0xffff0000u) * h4.w;
            }
            {
                uint32_t u0 = wreg[1][2 * j], u1 = wreg[1][2 * j + 1];
                a1 += __uint_as_float(u0 << 16) * h4.x;
                a1 += __uint_as_float(u0 & 0xffff0000u) * h4.y;
                a1 += __uint_as_float(u1 << 16) * h4.z;
                a1 += __uint_as_float(u1 & 0xffff0000u) * h4.w;
            }
            {
                uint32_t u0 = wreg[2][2 * j], u1 = wreg[2][2 * j + 1];
                a2 += __uint_as_float(u0 << 16) * h4.x;
                a2 += __uint_as_float(u0 & 0xffff0000u) * h4.y;
                a2 += __uint_as_float(u1 << 16) * h4.z;
                a2 += __uint_as_float(u1 & 0xffff0000u) * h4.w;
            }
            {
                uint32_t u0 = wreg[3][2 * j], u1 = wreg[3][2 * j + 1];
                a3 += __uint_as_float(u0 << 16) * h4.x;
                a3 += __uint_as_float(u0 & 0xffff0000u) * h4.y;
                a3 += __uint_as_float(u1 << 16) * h4.z;
                a3 += __uint_as_float(u1 & 0xffff0000u) * h4.w;
            }
        }
        // reduce over the 8 k-slices (lane bits 0..2)
#pragma unroll
        for (int m = 1; m < 8; m <<= 1) {
            a0 += __shfl_xor_sync(0xffffffffu, a0, m);
            a1 += __shfl_xor_sync(0xffffffffu, a1, m);
            a2 += __shfl_xor_sync(0xffffffffu, a2, m);
            a3 += __shfl_xor_sync(0xffffffffu, a3, m);
        }

        if (ks == 0) {
            float4 bs = *(const float4*)&bias[lr0];
            float4 gv;
            gv.x = a0 + bs.x + pv.x;
            gv.y = a1 + bs.y + pv.y;
            gv.z = a2 + bs.z + pv.z;
            gv.w = a3 + bs.w + pv.w;
            *(float4*)&gates[lr0] = gv;
            if (step + 1 < T_LEN) {
                int tn = dir ? (T_LEN - 2 - step) : (step + 1);
                pv = *(const float4*)&g_proj[(size_t)(b * T_LEN + tn) * NCOL + pcol];
            }
        }
        __syncthreads();

        if (tid < 64) {
            float iv = sigm_(gates[tid]);
            float fv = sigm_(gates[64 + tid]);
            float gg = tanh_(gates[128 + tid]);
            float ov = sigm_(gates[192 + tid]);
            creg = fv * creg + iv * gg;
            float hval = ov * tanh_(creg);
            g_hs[(size_t)((dir * T_LEN + te) * BATCH + b) * HID + r * 64 + tid] = hval;

            int np = p ^ 1;
            int cell = r * 64 + tid;
            int off = np * HBUF + (cell >> 5) * HSTR + (cell & 31);
            float* dst = hbuf + off;
            *dst = hval;                                    // local
            uint32_t la = (uint32_t)__cvta_generic_to_shared(dst);
#pragma unroll
            for (int pc = 0; pc < 4; pc++) {
                if (pc == r) continue;
                uint32_t ra;
                asm("mapa.shared::cluster.u32 %0, %1, %2;" : "=r"(ra) : "r"(la), "r"(pc));
                asm volatile("st.shared::cluster.f32 [%0], %1;" :: "r"(ra), "f"(hval)
                             : "memory");
            }
        }
        cluster_sync_();
        p ^= 1;
    }
}

// ============================================================================
// K3a/K3b: BN stats + fold into Linear
// ============================================================================
__global__ void bn_part() {
    const int ch = threadIdx.x;
    const int dir = ch >> 8, cc = ch & 255;
    const int s0 = blockIdx.x * 256;
    float sum = 0.f, sq = 0.f;
    const size_t base = (size_t)dir * T_LEN * BATCH * HID + cc;
#pragma unroll 4
    for (int i = 0; i < 256; i++) {
        float v = g_hs[base + (size_t)(s0 + i) * HID];
        sum += v; sq += v * v;
    }
    g_part[((size_t)blockIdx.x * 512 + ch) * 2]     = sum;
    g_part[((size_t)blockIdx.x * 512 + ch) * 2 + 1] = sq;
}

__global__ void bn_final(const float* __restrict__ gamma,
                         const float* __restrict__ beta,
                         const float* __restrict__ Wlin,
                         const float* __restrict__ blin) {
    __shared__ float red[512];
    const int ch = threadIdx.x;
    double s = 0.0, q = 0.0;
#pragma unroll 8
    for (int i = 0; i < 128; i++) {
        s += (double)g_part[((size_t)i * 512 + ch) * 2];
        q += (double)g_part[((size_t)i * 512 + ch) * 2 + 1];
    }
    const double n = 32768.0;
    float mean = (float)(s / n);
    float var  = (float)(q / n - (s / n) * (s / n));
    float A  = gamma[ch] * rsqrtf(var + 1e-5f);
    float Bc = beta[ch] - mean * A;

    g_wf[ch]       = Wlin[ch] * A;
    g_wf[512 + ch] = Wlin[512 + ch] * A;

    red[ch] = Wlin[ch] * Bc;
    __syncthreads();
    for (int o = 256; o > 0; o >>= 1) {
        if (ch < o) red[ch] += red[ch + o];
        __syncthreads();
    }
    if (ch == 0) g_zc[0] = blin[0] + red[0];
    __syncthreads();
    red[ch] = Wlin[512 + ch] * Bc;
    __syncthreads();
    for (int o = 256; o > 0; o >>= 1) {
        if (ch < o) red[ch] += red[ch + o];
        __syncthreads();
    }
    if (ch == 0) g_zc[1] = blin[1] + red[0];
}

// ============================================================================
// K4: posterior + gumbel argmax + sampled
// ============================================================================
__global__ void post_k(const float* __restrict__ u,
                       const float* __restrict__ e,
                       float* __restrict__ out) {
    const int s = blockIdx.x * 8 + (threadIdx.x >> 5);
    const int lane = threadIdx.x & 31;
    const int t = s >> 4, b = s & 15;
    const size_t base0 = (size_t)s * HID;
    const size_t base1 = (size_t)(32768 + s) * HID;

    float z0 = 0.f, z1 = 0.f;
#pragma unroll
    for (int i = 0; i < 8; i++) {
        int c = lane + 32 * i;
        float h0 = g_hs[base0 + c];
        float h1 = g_hs[base1 + c];
        z0 += g_wf[c] * h0 + g_wf[256 + c] * h1;
        z1 += g_wf[512 + c] * h0 + g_wf[768 + c] * h1;
    }
#pragma unroll
    for (int o = 16; o > 0; o >>= 1) {
        z0 += __shfl_xor_sync(0xffffffffu, z0, o);
        z1 += __shfl_xor_sync(0xffffffffu, z1, o);
    }
    if (lane == 0) {
        float a0 = (z0 + g_zc[0]) * 0.1f;
        float a1 = (z1 + g_zc[1]) * 0.1f;
        float m = fmaxf(a0, a1);
        float e0 = __expf(a0 - m), e1 = __expf(a1 - m);
        float inv = 1.f / (e0 + e1);
        size_t po = ((size_t)b * T_LEN + t) * 2;
        out[po]     = e0 * inv;
        out[po + 1] = e1 * inv;
        float u0 = u[po], u1 = u[po + 1];
        float gg0 = -logf(-logf(u0 + 1e-20f) + 1e-20f);
        float gg1 = -logf(-logf(u1 + 1e-20f) + 1e-20f);
        int ind = (a1 + gg1 > a0 + gg0) ? 1 : 0;
        g_sampled[b * T_LEN + t] = ind ? e[b * T_LEN + t] : 0.f;
    }
}

// ============================================================================
// K5: three successive median-5 pools
// ============================================================================
__device__ __forceinline__ float median5_(float v0, float v1, float v2,
                                          float v3, float v4) {
#define CSWP(a, b) { float _t = fminf(a, b); b = fmaxf(a, b); a = _t; }
    CSWP(v0, v1); CSWP(v1, v2); CSWP(v2, v3); CSWP(v3, v4);
    CSWP(v0, v1); CSWP(v1, v2); CSWP(v2, v3);
    CSWP(v0, v1); CSWP(v1, v2);
#undef CSWP
    return v2;
}

__global__ void medpool_k(float* __restrict__ out) {
    __shared__ float bufA[2048], bufB[2048];
    const int b = blockIdx.x, tid = threadIdx.x;
    for (int i = tid; i < 2048; i += 256) bufA[i] = g_sampled[b * 2048 + i];
    __syncthreads();
    float* src = bufA;
    float* dst = bufB;
    for (int pass = 0; pass < 3; pass++) {
        for (int i = tid; i < 2048; i += 256) {
            float v[5];
#pragma unroll
            for (int jj = 0; jj < 5; jj++) {
                int j = i + jj - 2;
                j = (j < 0) ? -j : ((j > 2047) ? (4094 - j) : j);
                v[jj] = src[j];
            }
            dst[i] = median5_(v[0], v[1], v[2], v[3], v[4]);
        }
        __syncthreads();
        float* tmp = src; src = dst; dst = tmp;
    }
    for (int i = tid; i < 2048; i += 256)
        out[65536 + b * 2048 + i] = src[i];
}

// ============================================================================
extern "C" void kernel_launch(void* const* d_in, const int* in_sizes, int n_in,
                              void* d_out, int out_size) {
    const float* x      = (const float*)d_in[0];
    const float* e      = (const float*)d_in[1];
    const float* u      = (const float*)d_in[2];
    const float* Wih_f  = (const float*)d_in[3];
    const float* Whh_f  = (const float*)d_in[4];
    const float* bih_f  = (const float*)d_in[5];
    const float* bhh_f  = (const float*)d_in[6];
    const float* Wih_b  = (const float*)d_in[7];
    const float* Whh_b  = (const float*)d_in[8];
    const float* bih_b  = (const float*)d_in[9];
    const float* bhh_b  = (const float*)d_in[10];
    const float* gamma  = (const float*)d_in[11];
    const float* beta   = (const float*)d_in[12];
    const float* Wlin   = (const float*)d_in[13];
    const float* blin   = (const float*)d_in[14];
    float* out = (float*)d_out;

    conv_x<<<dim3(64, 16, 16), dim3(32, 8)>>>(x);
    conv_w<<<4096, 256>>>(Wih_f, Wih_b);
    gemm_tc<<<dim3(16, 256), 256>>>();
    lstm_k<<<128, 512>>>(Whh_f, Whh_b, bih_f, bhh_f, bih_b, bhh_b);
    bn_part<<<128, 512>>>();
    bn_final<<<1, 512>>>(gamma, beta, Wlin, blin);
    post_k<<<4096, 256>>>(u, e, out);
    medpool_k<<<16, 256>>>(out);
}